// round 1
// baseline (speedup 1.0000x reference)
#include <cuda_runtime.h>
#include <math.h>

#define BATCH   32
#define TT      32
#define DIN     128
#define NS      512
#define ML      64
#define CTRLD   256
#define CIN     384      // DIN + 4*ML
#define INSTR_D 478
#define NHEADS  5        // 4 read + 1 write
#define NT      512
#define MEMP    65       // padded Mem row stride (floats)

// SMEM layout (floats)
#define OFF_MEM   0
#define OFF_BUF   (NS*MEMP)            // 33280  ; 5*512 scratch
#define OFF_RW    (OFF_BUF + 5*NS)     // 4*512
#define OFF_WW    (OFF_RW + 4*NS)      // 512
#define OFF_MN    (OFF_WW + NS)        // 512
#define OFF_RVEC  (OFF_MN + NS)        // 256
#define OFF_CTRL  (OFF_RVEC + 256)     // 384
#define OFF_H     (OFF_CTRL + CIN)     // 256
#define OFF_INSTR (OFF_H + CTRLD)      // 480
#define OFF_KVEC  (OFF_INSTR + 480)    // 5*64
#define OFF_EVEC  (OFF_KVEC + 320)     // 64
#define OFF_AVEC  (OFF_EVEC + 64)      // 64
#define OFF_HP    (OFF_AVEC + 64)      // 5*8 : [beta,g,t,s0,s1,s2,kn,-]
#define OFF_REDB  (OFF_HP + 40)        // 80
#define OFF_FIN   (OFF_REDB + 80)      // 8
#define SMEM_FLOATS (OFF_FIN + 8)

__device__ __forceinline__ float sigmoidf_(float v) { return 1.f / (1.f + expf(-v)); }
__device__ __forceinline__ float softplusf_(float v) { return v > 20.f ? v : log1pf(expf(v)); }

// block reduce of 5 values per thread (max or sum). Writes result to fin[0..4].
__device__ __forceinline__ void blockReduce5(float* v, float* redb, float* fin,
                                             int tid, bool domax) {
    const int lane = tid & 31, warp = tid >> 5;
#pragma unroll
    for (int o = 16; o > 0; o >>= 1) {
#pragma unroll
        for (int h = 0; h < NHEADS; ++h) {
            float other = __shfl_xor_sync(0xffffffffu, v[h], o);
            v[h] = domax ? fmaxf(v[h], other) : (v[h] + other);
        }
    }
    if (lane == 0) {
#pragma unroll
        for (int h = 0; h < NHEADS; ++h) redb[warp * NHEADS + h] = v[h];
    }
    __syncthreads();
    if (tid < NHEADS) {
        float acc = redb[tid];
#pragma unroll
        for (int w = 1; w < NT / 32; ++w) {
            float o = redb[w * NHEADS + tid];
            acc = domax ? fmaxf(acc, o) : (acc + o);
        }
        fin[tid] = acc;
    }
    __syncthreads();
}

__global__ __launch_bounds__(NT, 1)
void ntm_kernel(const float* __restrict__ x, const float* __restrict__ Wc,
                const float* __restrict__ bc, const float* __restrict__ hk,
                const float* __restrict__ hb, float* __restrict__ out)
{
    extern __shared__ float sm[];
    float* Mem   = sm + OFF_MEM;
    float* buf   = sm + OFF_BUF;
    float* rw    = sm + OFF_RW;
    float* ww    = sm + OFF_WW;
    float* Mn    = sm + OFF_MN;
    float* rvec  = sm + OFF_RVEC;
    float* ctrl  = sm + OFF_CTRL;
    float* hbuf  = sm + OFF_H;
    float* instr = sm + OFF_INSTR;
    float* kvec  = sm + OFF_KVEC;
    float* evec  = sm + OFF_EVEC;
    float* avec  = sm + OFF_AVEC;
    float* hp    = sm + OFF_HP;
    float* redb  = sm + OFF_REDB;
    float* fin   = sm + OFF_FIN;

    const int b   = blockIdx.x;
    const int tid = threadIdx.x;

    // ---- init state ----
    for (int i = tid; i < NS * MEMP; i += NT) Mem[i] = 0.f;
    for (int i = tid; i < 4 * NS; i += NT) rw[i] = 0.f;
    if (tid < NS) ww[tid] = 0.f;
    if (tid < 256) rvec[tid] = 0.f;
    __syncthreads();

    for (int t = 0; t < TT; ++t) {
        // ---- ctrl_in = [x_t, r.flatten()] ----
        if (tid < DIN)      ctrl[tid] = x[(b * TT + t) * DIN + tid];
        else if (tid < CIN) ctrl[tid] = rvec[tid - DIN];
        __syncthreads();

        // ---- mm1: h = tanh(ctrl @ Wc + bc)   Wc: [384,256] row-major ----
        {
            const int cg = tid & 63;     // 4-column group
            const int ks = tid >> 6;     // 8-way k split, 48 rows each
            float a0 = 0.f, a1 = 0.f, a2 = 0.f, a3 = 0.f;
            const float4* W4 = reinterpret_cast<const float4*>(Wc);
            const int k0 = ks * 48;
#pragma unroll 4
            for (int k = k0; k < k0 + 48; ++k) {
                float c = ctrl[k];
                float4 w = W4[k * 64 + cg];
                a0 = fmaf(c, w.x, a0); a1 = fmaf(c, w.y, a1);
                a2 = fmaf(c, w.z, a2); a3 = fmaf(c, w.w, a3);
            }
            reinterpret_cast<float4*>(buf)[ks * 64 + cg] = make_float4(a0, a1, a2, a3);
        }
        __syncthreads();
        if (tid < CTRLD) {
            float acc = bc[tid];
#pragma unroll
            for (int ks = 0; ks < 8; ++ks) acc += buf[ks * 256 + tid];
            hbuf[tid] = tanhf(acc);
        }
        __syncthreads();

        // ---- mm2: instr = h @ hk + hb   hk: [256,478] row-major ----
        {
            const int p  = tid & 255;    // column pair (float2), 239 pairs
            const int ks = tid >> 8;     // 2-way k split, 128 rows each
            if (p < 239) {
                float a0 = 0.f, a1 = 0.f;
                const float2* H2 = reinterpret_cast<const float2*>(hk);
                const int k0 = ks * 128;
#pragma unroll 4
                for (int k = k0; k < k0 + 128; ++k) {
                    float hv = hbuf[k];
                    float2 w = H2[k * 239 + p];
                    a0 = fmaf(hv, w.x, a0); a1 = fmaf(hv, w.y, a1);
                }
                buf[ks * 478 + 2 * p]     = a0;
                buf[ks * 478 + 2 * p + 1] = a1;
            }
        }
        __syncthreads();
        if (tid < INSTR_D) instr[tid] = buf[tid] + buf[478 + tid] + hb[tid];
        __syncthreads();

        // ---- parse heads ----
        if (tid < 320) {                 // k vectors: 5 heads x 64
            int h = tid >> 6, m = tid & 63;
            kvec[tid] = instr[(h < 4 ? h * 70 : 280) + m];
        } else if (tid < 384) {          // erase
            evec[tid - 320] = instr[350 + (tid - 320)];
        } else if (tid < 448) {          // add
            avec[tid - 384] = instr[414 + (tid - 384)];
        } else if (tid < 448 + NHEADS) { // scalar params
            int h = tid - 448;
            int base = (h < 4 ? h * 70 : 280);
            hp[h * 8 + 0] = expf(instr[base + 64]);             // beta
            hp[h * 8 + 1] = sigmoidf_(instr[base + 65]);        // g
            hp[h * 8 + 2] = softplusf_(instr[base + 69]) + 1.f; // t
            float s0 = instr[base + 66], s1 = instr[base + 67], s2 = instr[base + 68];
            float mx = fmaxf(s0, fmaxf(s1, s2));
            float e0 = expf(s0 - mx), e1 = expf(s1 - mx), e2 = expf(s2 - mx);
            float inv = 1.f / (e0 + e1 + e2);
            hp[h * 8 + 3] = e0 * inv; hp[h * 8 + 4] = e1 * inv; hp[h * 8 + 5] = e2 * inv;
        }
        __syncthreads();

        // ---- key norms + memory norms ----
        if (tid < NHEADS) {
            float s = 0.f;
#pragma unroll 8
            for (int m = 0; m < ML; ++m) { float v = kvec[tid * 64 + m]; s = fmaf(v, v, s); }
            hp[tid * 8 + 6] = sqrtf(s);
        }
        {
            float s = 0.f;
            const float* mr = Mem + tid * MEMP;
#pragma unroll 8
            for (int m = 0; m < ML; ++m) { float v = mr[m]; s = fmaf(v, v, s); }
            Mn[tid] = sqrtf(s);
        }
        __syncthreads();

        // ---- cosine sim, z = beta * sim ----
        float z[NHEADS];
        {
            float d0 = 0.f, d1 = 0.f, d2 = 0.f, d3 = 0.f, d4 = 0.f;
            const float* mr = Mem + tid * MEMP;
#pragma unroll 8
            for (int m = 0; m < ML; ++m) {
                float v = mr[m];
                d0 = fmaf(v, kvec[m],        d0);
                d1 = fmaf(v, kvec[64 + m],   d1);
                d2 = fmaf(v, kvec[128 + m],  d2);
                d3 = fmaf(v, kvec[192 + m],  d3);
                d4 = fmaf(v, kvec[256 + m],  d4);
            }
            float mn = Mn[tid];
            float d[5] = { d0, d1, d2, d3, d4 };
#pragma unroll
            for (int h = 0; h < NHEADS; ++h)
                z[h] = hp[h * 8 + 0] * (d[h] / (hp[h * 8 + 6] * mn + 1e-8f));
        }

        // ---- softmax over slots (stable) ----
        float tmp[NHEADS];
#pragma unroll
        for (int h = 0; h < NHEADS; ++h) tmp[h] = z[h];
        blockReduce5(tmp, redb, fin, tid, true);   // fin = max
        float ex[NHEADS];
#pragma unroll
        for (int h = 0; h < NHEADS; ++h) { ex[h] = expf(z[h] - fin[h]); tmp[h] = ex[h]; }
        blockReduce5(tmp, redb, fin, tid, false);  // fin = sum
        // ---- interpolate with previous weights -> wg in buf ----
#pragma unroll
        for (int h = 0; h < NHEADS; ++h) {
            float wc = ex[h] / fin[h];
            float wp = (h < 4) ? rw[h * NS + tid] : ww[tid];
            float g  = hp[h * 8 + 1];
            buf[h * NS + tid] = g * wc + (1.f - g) * wp;
        }
        __syncthreads();

        // ---- circular shift + sharpen ----
        float wt[NHEADS];
        {
            const int np1 = (tid + 1) & (NS - 1);
            const int nm1 = (tid + NS - 1) & (NS - 1);
#pragma unroll
            for (int h = 0; h < NHEADS; ++h) {
                float wsh = hp[h * 8 + 3] * buf[h * NS + np1]
                          + hp[h * 8 + 4] * buf[h * NS + tid]
                          + hp[h * 8 + 5] * buf[h * NS + nm1];
                wt[h] = powf(fmaxf(wsh, 0.f), hp[h * 8 + 2]);
                tmp[h] = wt[h];
            }
        }
        blockReduce5(tmp, redb, fin, tid, false);  // fin = sum(wt)
        float wwn;
#pragma unroll
        for (int h = 0; h < NHEADS; ++h) {
            float wn = wt[h] / (fin[h] + 1e-8f);
            if (h < 4) rw[h * NS + tid] = wn;
            else { ww[tid] = wn; wwn = wn; }
        }

        // ---- memory write (erase + add), row tid is exclusive to this thread ----
        {
            float* mr = Mem + tid * MEMP;
#pragma unroll 8
            for (int m = 0; m < ML; ++m)
                mr[m] = mr[m] * (1.f - wwn * evec[m]) + wwn * avec[m];
        }
        __syncthreads();

        // ---- read: r[i][m] = sum_n Mem[n][m] * rw[i][n] ----
        {
            const int half = tid >> 8;       // 2-way n split
            const int q    = tid & 255;
            const int ih   = q >> 6;         // read head
            const int m    = q & 63;
            float acc = 0.f;
            const int n0 = half * 256;
#pragma unroll 8
            for (int n = n0; n < n0 + 256; ++n)
                acc = fmaf(Mem[n * MEMP + m], rw[ih * NS + n], acc);
            buf[half * 256 + q] = acc;
        }
        __syncthreads();
        if (tid < 256) rvec[tid] = buf[tid] + buf[256 + tid];
        if (t == TT - 1 && tid < CTRLD) out[b * CTRLD + tid] = hbuf[tid];
        __syncthreads();
    }
}

extern "C" void kernel_launch(void* const* d_in, const int* in_sizes, int n_in,
                              void* d_out, int out_size) {
    const float* x  = (const float*)d_in[0];
    const float* Wc = (const float*)d_in[1];
    const float* bc = (const float*)d_in[2];
    const float* hk = (const float*)d_in[3];
    const float* hb = (const float*)d_in[4];
    float* out = (float*)d_out;

    const size_t smem = SMEM_FLOATS * sizeof(float);
    cudaFuncSetAttribute(ntm_kernel, cudaFuncAttributeMaxDynamicSharedMemorySize, (int)smem);
    ntm_kernel<<<BATCH, NT, smem>>>(x, Wc, bc, hk, hb, out);
}

// round 3
// speedup vs baseline: 1.5733x; 1.5733x over previous
#include <cuda_runtime.h>
#include <cstdint>
#include <math.h>

#define BATCH   32
#define TT      32
#define DIN     128
#define NS      512
#define CSZ     4        // cluster size (CTAs per batch)
#define SL      128      // slots per CTA
#define ML      64
#define CTRLD   256
#define CIN     384
#define NHEADS  5
#define NT      512
#define MEMP    65

// ---- SMEM layout (float offsets) ----
#define OFF_MEM   0                       // 128*65 = 8320
#define OFF_BUF   (SL*MEMP)               // 2048 scratch
#define OFF_RW    (OFF_BUF + 2048)        // 4*128
#define OFF_WW    (OFF_RW + 512)          // 128
#define OFF_WWB   (OFF_WW + 128)          // 128 staged write-weight
#define OFF_RVEC  (OFF_WWB + 128)         // 256
#define OFF_CTRL  (OFF_RVEC + 256)        // 384
#define OFF_HX    (OFF_CTRL + 384)        // 256 gathered h
#define OFF_IX    (OFF_HX + 256)          // 480 gathered instr
#define OFF_KV    (OFF_IX + 480)          // 320
#define OFF_EV    (OFF_KV + 320)          // 64
#define OFF_AV    (OFF_EV + 64)           // 64
#define OFF_HP    (OFF_AV + 64)           // 40 : per head [beta,g,t,s0,s1,s2,kn,-]
#define OFF_STATS (OFF_HP + 40)           // 40 : [cta][head][max,sumexp]
#define OFF_WG    (OFF_STATS + 40)        // 5*130 = 650 (1-slot halos)
#define OFF_SSUM  (OFF_WG + 650)          // 20 : [cta][head]
#define OFF_RPART (OFF_SSUM + 20)         // 4*256
#define OFF_REDB  (OFF_RPART + 1024)      // 16 warps * 5
#define OFF_FIN   (OFF_REDB + 80)         // 8
#define OFF_GMX   (OFF_FIN + 8)           // 5
#define OFF_GSM   (OFF_GMX + 5)           // 5
#define SMEM_FLOATS (OFF_GSM + 5)

__device__ __forceinline__ float sigmoidf_(float v) { return 1.f / (1.f + expf(-v)); }
__device__ __forceinline__ float softplusf_(float v) { return v > 20.f ? v : log1pf(expf(v)); }

__device__ __forceinline__ uint32_t smem_u32(const void* p) {
    uint32_t a;
    asm("{ .reg .u64 t; cvta.to.shared.u64 t, %1; cvt.u32.u64 %0, t; }" : "=r"(a) : "l"(p));
    return a;
}
__device__ __forceinline__ uint32_t mapa_u32(uint32_t a, uint32_t rank) {
    uint32_t r;
    asm("mapa.shared::cluster.u32 %0, %1, %2;" : "=r"(r) : "r"(a), "r"(rank));
    return r;
}
__device__ __forceinline__ void st_remote(uint32_t a, float v) {
    asm volatile("st.shared::cluster.f32 [%0], %1;" :: "r"(a), "f"(v) : "memory");
}
__device__ __forceinline__ uint32_t ctarank() {
    uint32_t r; asm("mov.u32 %0, %%cluster_ctarank;" : "=r"(r)); return r;
}
#define CLUSTER_SYNC() do { \
    asm volatile("barrier.cluster.arrive.aligned;" ::: "memory"); \
    asm volatile("barrier.cluster.wait.aligned;" ::: "memory"); } while (0)

// block reduce of 5 values per thread (max or sum). Result in fin[0..4].
__device__ __forceinline__ void blockReduce5(float* v, float* redb, float* fin,
                                             int tid, bool domax) {
    const int lane = tid & 31, warp = tid >> 5;
#pragma unroll
    for (int o = 16; o > 0; o >>= 1) {
#pragma unroll
        for (int h = 0; h < NHEADS; ++h) {
            float other = __shfl_xor_sync(0xffffffffu, v[h], o);
            v[h] = domax ? fmaxf(v[h], other) : (v[h] + other);
        }
    }
    if (lane == 0) {
#pragma unroll
        for (int h = 0; h < NHEADS; ++h) redb[warp * NHEADS + h] = v[h];
    }
    __syncthreads();
    if (tid < NHEADS) {
        float acc = redb[tid];
#pragma unroll
        for (int w = 1; w < NT / 32; ++w) {
            float o = redb[w * NHEADS + tid];
            acc = domax ? fmaxf(acc, o) : (acc + o);
        }
        fin[tid] = acc;
    }
    __syncthreads();
}

__global__ __launch_bounds__(NT, 1) __cluster_dims__(CSZ, 1, 1)
void ntm_kernel(const float* __restrict__ x, const float* __restrict__ Wc,
                const float* __restrict__ bc, const float* __restrict__ hk,
                const float* __restrict__ hb, float* __restrict__ out)
{
    extern __shared__ float sm[];
    float* Mem   = sm + OFF_MEM;
    float* buf   = sm + OFF_BUF;
    float* rwL   = sm + OFF_RW;
    float* wwL   = sm + OFF_WW;
    float* wwb   = sm + OFF_WWB;
    float* rvec  = sm + OFF_RVEC;
    float* ctrl  = sm + OFF_CTRL;
    float* hx    = sm + OFF_HX;
    float* ix    = sm + OFF_IX;
    float* kvec  = sm + OFF_KV;
    float* evec  = sm + OFF_EV;
    float* avec  = sm + OFF_AV;
    float* hp    = sm + OFF_HP;
    float* stats = sm + OFF_STATS;
    float* wgb   = sm + OFF_WG;
    float* ssum  = sm + OFF_SSUM;
    float* rpart = sm + OFF_RPART;
    float* redb  = sm + OFF_REDB;
    float* fin   = sm + OFF_FIN;
    float* gmx   = sm + OFF_GMX;
    float* gsm   = sm + OFF_GSM;

    const int tid = threadIdx.x;
    const int b   = blockIdx.x >> 2;
    const uint32_t r = ctarank();
    const uint32_t left  = (r + 3) & 3;
    const uint32_t right = (r + 1) & 3;

    const uint32_t sbase = smem_u32(sm);
    uint32_t pb[CSZ];
#pragma unroll
    for (int c = 0; c < CSZ; ++c) pb[c] = mapa_u32(sbase, c);

    // ---- init local state ----
    for (int i = tid; i < SL * MEMP; i += NT) Mem[i] = 0.f;
    if (tid < 512) rwL[tid] = 0.f;
    if (tid < SL)  wwL[tid] = 0.f;
    if (tid < CTRLD) rvec[tid] = 0.f;
    __syncthreads();
    CLUSTER_SYNC();   // all peers live + zeroed before any DSMEM traffic

    for (int t = 0; t < TT; ++t) {
        // ---- A: ctrl = [x_t, rvec] ----
        if (tid < DIN)      ctrl[tid] = x[(b * TT + t) * DIN + tid];
        else if (tid < CIN) ctrl[tid] = rvec[tid - DIN];
        __syncthreads();

        // ---- B: mm1 column chunk (64 cols) ----
        {
            const int cg = tid & 15;         // float4 group -> 4 cols
            const int ks = tid >> 4;         // 32-way k split, 12 rows each
            const float4* W4 = reinterpret_cast<const float4*>(Wc);
            float a0 = 0.f, a1 = 0.f, a2 = 0.f, a3 = 0.f;
            const int gidx = (int)r * 16 + cg;
            const int k0 = ks * 12;
#pragma unroll
            for (int k = k0; k < k0 + 12; ++k) {
                float c = ctrl[k];
                float4 w = W4[k * 64 + gidx];
                a0 = fmaf(c, w.x, a0); a1 = fmaf(c, w.y, a1);
                a2 = fmaf(c, w.z, a2); a3 = fmaf(c, w.w, a3);
            }
            reinterpret_cast<float4*>(buf)[ks * 16 + cg] = make_float4(a0, a1, a2, a3);
        }
        __syncthreads();
        if (tid < 64) {
            float acc = bc[r * 64 + tid];
#pragma unroll
            for (int ks = 0; ks < 32; ++ks) acc += buf[ks * 64 + tid];
            float h = tanhf(acc);
            const int gcol = (int)r * 64 + tid;
            hx[gcol] = h;
#pragma unroll
            for (int c = 0; c < CSZ; ++c)
                if (c != (int)r) st_remote(pb[c] + (OFF_HX + gcol) * 4, h);
            if (t == TT - 1) out[b * CTRLD + gcol] = h;
        }
        CLUSTER_SYNC();  // CS1: full h everywhere

        // ---- C: mm2 column chunk (120/120/120/118 cols) ----
        {
            const int c0 = (int)r * 120;
            const int ncols  = (r == 3) ? 118 : 120;
            const int npairs = ncols >> 1;
            const int p  = tid & 63;
            const int ks = tid >> 6;         // 8-way k split, 32 rows each
            if (p < npairs) {
                const float2* H2 = reinterpret_cast<const float2*>(hk);
                const int pj = (int)r * 60 + p;
                float a0 = 0.f, a1 = 0.f;
                const int k0 = ks * 32;
#pragma unroll 4
                for (int k = k0; k < k0 + 32; ++k) {
                    float hv = hx[k];
                    float2 w = H2[k * 239 + pj];
                    a0 = fmaf(hv, w.x, a0); a1 = fmaf(hv, w.y, a1);
                }
                buf[ks * 128 + 2 * p]     = a0;
                buf[ks * 128 + 2 * p + 1] = a1;
            }
            __syncthreads();
            if (tid < ncols) {
                float v = hb[c0 + tid];
#pragma unroll
                for (int ks2 = 0; ks2 < 8; ++ks2) v += buf[ks2 * 128 + tid];
                ix[c0 + tid] = v;
#pragma unroll
                for (int c = 0; c < CSZ; ++c)
                    if (c != (int)r) st_remote(pb[c] + (OFF_IX + c0 + tid) * 4, v);
            }
        }
        CLUSTER_SYNC();  // CS2: full instr everywhere

        // ---- D: parse heads (replicated) ----
        if (tid < 320) {
            int h = tid >> 6, m = tid & 63;
            kvec[tid] = ix[(h < 4 ? h * 70 : 280) + m];
        } else if (tid < 384) {
            evec[tid - 320] = ix[350 + (tid - 320)];
        } else if (tid < 448) {
            avec[tid - 384] = ix[414 + (tid - 384)];
        } else if (tid < 448 + NHEADS) {
            int h = tid - 448;
            int base = (h < 4 ? h * 70 : 280);
            hp[h * 8 + 0] = expf(ix[base + 64]);
            hp[h * 8 + 1] = sigmoidf_(ix[base + 65]);
            hp[h * 8 + 2] = softplusf_(ix[base + 69]) + 1.f;
            float s0 = ix[base + 66], s1 = ix[base + 67], s2 = ix[base + 68];
            float mx = fmaxf(s0, fmaxf(s1, s2));
            float e0 = expf(s0 - mx), e1 = expf(s1 - mx), e2 = expf(s2 - mx);
            float inv = 1.f / (e0 + e1 + e2);
            hp[h * 8 + 3] = e0 * inv; hp[h * 8 + 4] = e1 * inv; hp[h * 8 + 5] = e2 * inv;
            float s = 0.f;
#pragma unroll 8
            for (int m = 0; m < ML; ++m) { float v = ix[base + m]; s = fmaf(v, v, s); }
            hp[h * 8 + 6] = sqrtf(s);
        }
        __syncthreads();

        // ---- E: sim + norm over local slots (4 threads/slot) ----
        const int s  = tid >> 2;     // local slot 0..127
        const int pq = tid & 3;      // m-quarter
        float z[NHEADS], ex[NHEADS], lmax[NHEADS];
        {
            float d0 = 0.f, d1 = 0.f, d2 = 0.f, d3 = 0.f, d4 = 0.f, nn = 0.f;
            const float* mr = Mem + s * MEMP;
            const int m0 = pq * 16;
#pragma unroll
            for (int m = m0; m < m0 + 16; ++m) {
                float v = mr[m];
                nn = fmaf(v, v, nn);
                d0 = fmaf(v, kvec[m],       d0);
                d1 = fmaf(v, kvec[64 + m],  d1);
                d2 = fmaf(v, kvec[128 + m], d2);
                d3 = fmaf(v, kvec[192 + m], d3);
                d4 = fmaf(v, kvec[256 + m], d4);
            }
            float d[5] = { d0, d1, d2, d3, d4 };
#pragma unroll
            for (int o = 1; o <= 2; o <<= 1) {
#pragma unroll
                for (int h = 0; h < NHEADS; ++h) d[h] += __shfl_xor_sync(0xffffffffu, d[h], o);
                nn += __shfl_xor_sync(0xffffffffu, nn, o);
            }
            float mn = sqrtf(nn);
#pragma unroll
            for (int h = 0; h < NHEADS; ++h)
                z[h] = hp[h * 8 + 0] * (d[h] / (hp[h * 8 + 6] * mn + 1e-8f));
        }
        // local softmax stats
        float tmp[NHEADS];
#pragma unroll
        for (int h = 0; h < NHEADS; ++h) tmp[h] = z[h];
        blockReduce5(tmp, redb, fin, tid, true);   // local max
#pragma unroll
        for (int h = 0; h < NHEADS; ++h) {
            lmax[h] = fin[h];
            ex[h] = expf(z[h] - lmax[h]);
            tmp[h] = (pq == 0) ? ex[h] : 0.f;
        }
        blockReduce5(tmp, redb, fin, tid, false);  // local sum(exp)
        if (tid < NHEADS) {
            float lm = lmax[tid], ls = fin[tid];
            float* st0 = stats + r * 10 + tid * 2;
            st0[0] = lm; st0[1] = ls;
#pragma unroll
            for (int c = 0; c < CSZ; ++c)
                if (c != (int)r) {
                    uint32_t a = pb[c] + (OFF_STATS + r * 10 + tid * 2) * 4;
                    st_remote(a, lm); st_remote(a + 4, ls);
                }
        }
        CLUSTER_SYNC();  // CS3: stats everywhere
        if (tid < NHEADS) {
            float gm = stats[tid * 2];
#pragma unroll
            for (int c = 1; c < CSZ; ++c) gm = fmaxf(gm, stats[c * 10 + tid * 2]);
            float gs = 0.f;
#pragma unroll
            for (int c = 0; c < CSZ; ++c)
                gs += stats[c * 10 + tid * 2 + 1] * expf(stats[c * 10 + tid * 2] - gm);
            gmx[tid] = gm; gsm[tid] = gs;
        }
        __syncthreads();

        // ---- wg for local slots + halo exchange ----
        if (pq == 0) {
            float wgv[NHEADS];
#pragma unroll
            for (int h = 0; h < NHEADS; ++h) {
                float wc = ex[h] * expf(lmax[h] - gmx[h]) / gsm[h];
                float wp = (h < 4) ? rwL[h * SL + s] : wwL[s];
                float g  = hp[h * 8 + 1];
                wgv[h] = g * wc + (1.f - g) * wp;
                wgb[h * 130 + s + 1] = wgv[h];
            }
            if (s == 0) {
#pragma unroll
                for (int h = 0; h < NHEADS; ++h)
                    st_remote(pb[left] + (OFF_WG + h * 130 + 129) * 4, wgv[h]);
            }
            if (s == SL - 1) {
#pragma unroll
                for (int h = 0; h < NHEADS; ++h)
                    st_remote(pb[right] + (OFF_WG + h * 130 + 0) * 4, wgv[h]);
            }
        }
        CLUSTER_SYNC();  // CS4: wg halos present

        // ---- F: shift + sharpen ----
        float wt[NHEADS];
        if (tid < SL) {
#pragma unroll
            for (int h = 0; h < NHEADS; ++h) {
                float wsh = hp[h * 8 + 3] * wgb[h * 130 + tid + 2]
                          + hp[h * 8 + 4] * wgb[h * 130 + tid + 1]
                          + hp[h * 8 + 5] * wgb[h * 130 + tid];
                wt[h] = powf(fmaxf(wsh, 0.f), hp[h * 8 + 2]);
            }
        }
#pragma unroll
        for (int h = 0; h < NHEADS; ++h) tmp[h] = (tid < SL) ? wt[h] : 0.f;
        blockReduce5(tmp, redb, fin, tid, false);  // local sum(wt)
        if (tid < NHEADS) {
            float lv = fin[tid];
            ssum[r * 5 + tid] = lv;
#pragma unroll
            for (int c = 0; c < CSZ; ++c)
                if (c != (int)r) st_remote(pb[c] + (OFF_SSUM + r * 5 + tid) * 4, lv);
        }
        CLUSTER_SYNC();  // CS5: sharpen sums everywhere
        if (tid < SL) {
#pragma unroll
            for (int h = 0; h < NHEADS; ++h) {
                float gsumw = ssum[h] + ssum[5 + h] + ssum[10 + h] + ssum[15 + h];
                float wn = wt[h] / (gsumw + 1e-8f);
                if (h < 4) rwL[h * SL + tid] = wn;
                else { wwL[tid] = wn; wwb[tid] = wn; }
            }
        }
        __syncthreads();

        // ---- G: memory write (local slots), 4 threads/row ----
        {
            float wv = wwb[s];
            float* mr = Mem + s * MEMP;
            const int m0 = pq * 16;
#pragma unroll
            for (int m = m0; m < m0 + 16; ++m)
                mr[m] = mr[m] * (1.f - wv * evec[m]) + wv * avec[m];
        }
        __syncthreads();

        // ---- H: read partials over local slots ----
        {
            const int half = tid >> 8;        // 2-way slot split (64 each)
            const int q    = tid & 255;
            const int ih   = q >> 6;
            const int m    = q & 63;
            float acc = 0.f;
            const int n0 = half * 64;
#pragma unroll 8
            for (int n = n0; n < n0 + 64; ++n)
                acc = fmaf(Mem[n * MEMP + m], rwL[ih * SL + n], acc);
            buf[half * 256 + q] = acc;
        }
        __syncthreads();
        if (tid < 256) {
            float v = buf[tid] + buf[256 + tid];
            rpart[r * 256 + tid] = v;
#pragma unroll
            for (int c = 0; c < CSZ; ++c)
                if (c != (int)r) st_remote(pb[c] + (OFF_RPART + r * 256 + tid) * 4, v);
        }
        CLUSTER_SYNC();  // CS6: read partials everywhere
        if (tid < 256)
            rvec[tid] = rpart[tid] + rpart[256 + tid] + rpart[512 + tid] + rpart[768 + tid];
        __syncthreads();
    }
}

extern "C" void kernel_launch(void* const* d_in, const int* in_sizes, int n_in,
                              void* d_out, int out_size) {
    const float* x  = (const float*)d_in[0];
    const float* Wc = (const float*)d_in[1];
    const float* bc = (const float*)d_in[2];
    const float* hk = (const float*)d_in[3];
    const float* hb = (const float*)d_in[4];
    float* out = (float*)d_out;

    const size_t smem = SMEM_FLOATS * sizeof(float);
    cudaFuncSetAttribute(ntm_kernel, cudaFuncAttributeMaxDynamicSharedMemorySize, (int)smem);
    ntm_kernel<<<BATCH * CSZ, NT, smem>>>(x, Wc, bc, hk, hb, out);
}

// round 4
// speedup vs baseline: 1.8255x; 1.1603x over previous
#include <cuda_runtime.h>
#include <cstdint>
#include <math.h>

#define BATCH   32
#define TT      32
#define DIN     128
#define CSZ     4        // CTAs per batch (cluster)
#define SL      128      // slots per CTA
#define ML      64
#define CTRLD   256
#define CIN     384
#define NHEADS  5
#define NT      512
#define MEMP    65
#define KC1     184      // mm1 k-rows cached in SMEM (rest streamed)

// ---- SMEM layout (float offsets) ----
#define OFF_MEM   0                        // 128*65 = 8320
#define OFF_BUF   8320                     // 2048 scratch
#define OFF_RW4   10368                    // 128*4 read weights [slot][head] (float4)
#define OFF_WW    10880                    // 128
#define OFF_WWB   11008                    // 128
#define OFF_RVEC  11136                    // 256
#define OFF_CTRL  11392                    // 384
#define OFF_HX    11776                    // 256
#define OFF_IX    12032                    // 480
#define OFF_KV    12512                    // 320 (5 heads x 64, float4-aligned)
#define OFF_EV    12832                    // 64
#define OFF_AV    12896                    // 64
#define OFF_HP    12960                    // 40 : per head [beta,g,t,s0,s1,s2,kn,-]
#define OFF_STATS 13000                    // 40 : [cta][head][max,sumexp]
#define OFF_WG    13040                    // 5*130 (with halos)
#define OFF_HALO  13690                    // 20 : haloL[h][ex,wp] (0..9), haloR (10..19)
#define OFF_SSUM  13710                    // 20
#define OFF_RPART 13730                    // 4*256
#define OFF_REDB  14754                    // 80
#define OFF_FIN   14834                    // 8
#define OFF_GMX   14842                    // 5
#define OFF_GSM   14847                    // 5
#define OFF_SWC   14852                    // 184*64 = 11776 (mm1 cache, float4-aligned)
#define OFF_SHK   26628                    // 256*120 = 30720 (mm2 cache, float2-aligned)
#define SMEM_FLOATS 57348                  // 229392 bytes

__device__ __forceinline__ float sigmoidf_(float v) { return 1.f / (1.f + __expf(-v)); }
__device__ __forceinline__ float softplusf_(float v) { return v > 20.f ? v : log1pf(__expf(v)); }

__device__ __forceinline__ uint32_t smem_u32(const void* p) {
    uint32_t a;
    asm("{ .reg .u64 t; cvta.to.shared.u64 t, %1; cvt.u32.u64 %0, t; }" : "=r"(a) : "l"(p));
    return a;
}
__device__ __forceinline__ uint32_t mapa_u32(uint32_t a, uint32_t rank) {
    uint32_t r;
    asm("mapa.shared::cluster.u32 %0, %1, %2;" : "=r"(r) : "r"(a), "r"(rank));
    return r;
}
__device__ __forceinline__ void st_remote(uint32_t a, float v) {
    asm volatile("st.shared::cluster.f32 [%0], %1;" :: "r"(a), "f"(v) : "memory");
}
__device__ __forceinline__ uint32_t ctarank() {
    uint32_t r; asm("mov.u32 %0, %%cluster_ctarank;" : "=r"(r)); return r;
}
#define CLUSTER_SYNC() do { \
    asm volatile("barrier.cluster.arrive.aligned;" ::: "memory"); \
    asm volatile("barrier.cluster.wait.aligned;" ::: "memory"); } while (0)

// block reduce of 5 values per thread (max or sum). Result in fin[0..4].
__device__ __forceinline__ void blockReduce5(float* v, float* redb, float* fin,
                                             int tid, bool domax) {
    const int lane = tid & 31, warp = tid >> 5;
#pragma unroll
    for (int o = 16; o > 0; o >>= 1) {
#pragma unroll
        for (int h = 0; h < NHEADS; ++h) {
            float other = __shfl_xor_sync(0xffffffffu, v[h], o);
            v[h] = domax ? fmaxf(v[h], other) : (v[h] + other);
        }
    }
    if (lane == 0) {
#pragma unroll
        for (int h = 0; h < NHEADS; ++h) redb[warp * NHEADS + h] = v[h];
    }
    __syncthreads();
    if (tid < NHEADS) {
        float acc = redb[tid];
#pragma unroll
        for (int w = 1; w < NT / 32; ++w) {
            float o = redb[w * NHEADS + tid];
            acc = domax ? fmaxf(acc, o) : (acc + o);
        }
        fin[tid] = acc;
    }
    __syncthreads();
}

__global__ __launch_bounds__(NT, 1) __cluster_dims__(CSZ, 1, 1)
void ntm_kernel(const float* __restrict__ x, const float* __restrict__ Wc,
                const float* __restrict__ bc, const float* __restrict__ hk,
                const float* __restrict__ hb, float* __restrict__ out)
{
    extern __shared__ float sm[];
    float* Mem   = sm + OFF_MEM;
    float* buf   = sm + OFF_BUF;
    float* rw4   = sm + OFF_RW4;            // [slot][4 heads]
    float4* RW4  = reinterpret_cast<float4*>(rw4);
    float* wwL   = sm + OFF_WW;
    float* wwb   = sm + OFF_WWB;
    float* rvec  = sm + OFF_RVEC;
    float* ctrl  = sm + OFF_CTRL;
    float* hx    = sm + OFF_HX;
    float* ix    = sm + OFF_IX;
    float* kvec  = sm + OFF_KV;
    float4* KV4  = reinterpret_cast<float4*>(kvec);
    float* evec  = sm + OFF_EV;
    float4* EV4  = reinterpret_cast<float4*>(evec);
    float* avec  = sm + OFF_AV;
    float4* AV4  = reinterpret_cast<float4*>(avec);
    float* hp    = sm + OFF_HP;
    float* stats = sm + OFF_STATS;
    float* wgb   = sm + OFF_WG;
    float* halo  = sm + OFF_HALO;
    float* ssum  = sm + OFF_SSUM;
    float* rpart = sm + OFF_RPART;
    float* redb  = sm + OFF_REDB;
    float* fin   = sm + OFF_FIN;
    float* gmx   = sm + OFF_GMX;
    float* gsm   = sm + OFF_GSM;
    float4* SWC4 = reinterpret_cast<float4*>(sm + OFF_SWC);
    float2* SHK2 = reinterpret_cast<float2*>(sm + OFF_SHK);

    const int tid = threadIdx.x;
    const int b   = blockIdx.x >> 2;
    const uint32_t r = ctarank();
    const uint32_t left  = (r + 3) & 3;
    const uint32_t right = (r + 1) & 3;
    const int npairs = (r == 3) ? 59 : 60;   // mm2 column pairs for this CTA
    const int ncols  = npairs * 2;

    const uint32_t sbase = smem_u32(sm);
    uint32_t pb[CSZ];
#pragma unroll
    for (int c = 0; c < CSZ; ++c) pb[c] = mapa_u32(sbase, c);

    // ---- init local state + weight caches ----
    for (int i = tid; i < SL * MEMP; i += NT) Mem[i] = 0.f;
    if (tid < 512) rw4[tid] = 0.f;
    if (tid < SL)  wwL[tid] = 0.f;
    if (tid < CTRLD) rvec[tid] = 0.f;
    {
        const float4* W4 = reinterpret_cast<const float4*>(Wc);
        for (int i = tid; i < KC1 * 16; i += NT)
            SWC4[i] = W4[(i >> 4) * 64 + (int)r * 16 + (i & 15)];
        const float2* H2 = reinterpret_cast<const float2*>(hk);
        for (int i = tid; i < 256 * 60; i += NT) {
            int k = i / 60, p = i - k * 60;
            if (p < npairs) SHK2[k * 60 + p] = H2[k * 239 + (int)r * 60 + p];
        }
    }
    __syncthreads();
    CLUSTER_SYNC();   // all peers live + zeroed before any DSMEM traffic

    for (int t = 0; t < TT; ++t) {
        // ---- A: ctrl = [x_t, rvec] ----
        if (tid < DIN)      ctrl[tid] = x[(b * TT + t) * DIN + tid];
        else if (tid < CIN) ctrl[tid] = rvec[tid - DIN];
        __syncthreads();

        // ---- B: mm1 column chunk (64 cols), k<KC1 from SMEM cache ----
        {
            const int cg = tid & 15;         // float4 group -> 4 cols
            const int ks = tid >> 4;         // 32-way k split, 12 rows each
            const float4* W4 = reinterpret_cast<const float4*>(Wc);
            const int gidx = (int)r * 16 + cg;
            float a0 = 0.f, a1 = 0.f, a2 = 0.f, a3 = 0.f;
            const int k0 = ks * 12;
#pragma unroll
            for (int k = k0; k < k0 + 12; ++k) {
                float c = ctrl[k];
                float4 w = (k < KC1) ? SWC4[k * 16 + cg] : W4[k * 64 + gidx];
                a0 = fmaf(c, w.x, a0); a1 = fmaf(c, w.y, a1);
                a2 = fmaf(c, w.z, a2); a3 = fmaf(c, w.w, a3);
            }
            reinterpret_cast<float4*>(buf)[ks * 16 + cg] = make_float4(a0, a1, a2, a3);
        }
        __syncthreads();
        if (tid < 64) {
            float acc = bc[r * 64 + tid];
#pragma unroll
            for (int ks = 0; ks < 32; ++ks) acc += buf[ks * 64 + tid];
            float h = tanhf(acc);
            const int gcol = (int)r * 64 + tid;
            hx[gcol] = h;
#pragma unroll
            for (int c = 0; c < CSZ; ++c)
                if (c != (int)r) st_remote(pb[c] + (OFF_HX + gcol) * 4, h);
            if (t == TT - 1) out[b * CTRLD + gcol] = h;
        }
        CLUSTER_SYNC();  // CS1: full h everywhere

        // ---- C: mm2 column chunk from SMEM cache ----
        {
            const int p  = tid & 63;
            const int ks = tid >> 6;         // 8-way k split, 32 rows each
            if (p < npairs) {
                float a0 = 0.f, a1 = 0.f;
                const int k0 = ks * 32;
#pragma unroll 8
                for (int k = k0; k < k0 + 32; ++k) {
                    float hv = hx[k];
                    float2 w = SHK2[k * 60 + p];
                    a0 = fmaf(hv, w.x, a0); a1 = fmaf(hv, w.y, a1);
                }
                buf[ks * 128 + 2 * p]     = a0;
                buf[ks * 128 + 2 * p + 1] = a1;
            }
            __syncthreads();
            const int c0 = (int)r * 120;
            if (tid < ncols) {
                float v = hb[c0 + tid];
#pragma unroll
                for (int ks2 = 0; ks2 < 8; ++ks2) v += buf[ks2 * 128 + tid];
                ix[c0 + tid] = v;
#pragma unroll
                for (int c = 0; c < CSZ; ++c)
                    if (c != (int)r) st_remote(pb[c] + (OFF_IX + c0 + tid) * 4, v);
            }
        }
        CLUSTER_SYNC();  // CS2: full instr everywhere

        // ---- D: parse heads (replicated) ----
        if (tid < 320) {
            int h = tid >> 6, m = tid & 63;
            kvec[tid] = ix[(h < 4 ? h * 70 : 280) + m];
        } else if (tid < 384) {
            evec[tid - 320] = ix[350 + (tid - 320)];
        } else if (tid < 448) {
            avec[tid - 384] = ix[414 + (tid - 384)];
        } else if (tid < 448 + NHEADS) {
            int h = tid - 448;
            int base = (h < 4 ? h * 70 : 280);
            hp[h * 8 + 0] = __expf(ix[base + 64]);
            hp[h * 8 + 1] = sigmoidf_(ix[base + 65]);
            hp[h * 8 + 2] = softplusf_(ix[base + 69]) + 1.f;
            float s0 = ix[base + 66], s1 = ix[base + 67], s2 = ix[base + 68];
            float mx = fmaxf(s0, fmaxf(s1, s2));
            float e0 = __expf(s0 - mx), e1 = __expf(s1 - mx), e2 = __expf(s2 - mx);
            float inv = 1.f / (e0 + e1 + e2);
            hp[h * 8 + 3] = e0 * inv; hp[h * 8 + 4] = e1 * inv; hp[h * 8 + 5] = e2 * inv;
            float s = 0.f;
#pragma unroll 8
            for (int m = 0; m < ML; ++m) { float v = ix[base + m]; s = fmaf(v, v, s); }
            hp[h * 8 + 6] = sqrtf(s);
        }
        __syncthreads();

        // ---- E: sim + norm over local slots (4 threads/slot, kvec via float4) ----
        const int s  = tid >> 2;     // local slot
        const int pq = tid & 3;      // m-quarter
        float z[NHEADS], ex[NHEADS], lmax[NHEADS];
        {
            float d[NHEADS] = {0.f, 0.f, 0.f, 0.f, 0.f};
            float nn = 0.f;
            const float* mr = Mem + s * MEMP + pq * 16;
#pragma unroll
            for (int j = 0; j < 4; ++j) {
                float m0 = mr[4 * j], m1 = mr[4 * j + 1], m2 = mr[4 * j + 2], m3 = mr[4 * j + 3];
                nn = fmaf(m0, m0, nn); nn = fmaf(m1, m1, nn);
                nn = fmaf(m2, m2, nn); nn = fmaf(m3, m3, nn);
#pragma unroll
                for (int h = 0; h < NHEADS; ++h) {
                    float4 kq = KV4[h * 16 + pq * 4 + j];
                    d[h] = fmaf(m0, kq.x, d[h]); d[h] = fmaf(m1, kq.y, d[h]);
                    d[h] = fmaf(m2, kq.z, d[h]); d[h] = fmaf(m3, kq.w, d[h]);
                }
            }
#pragma unroll
            for (int o = 1; o <= 2; o <<= 1) {
#pragma unroll
                for (int h = 0; h < NHEADS; ++h) d[h] += __shfl_xor_sync(0xffffffffu, d[h], o);
                nn += __shfl_xor_sync(0xffffffffu, nn, o);
            }
            float mn = sqrtf(nn);
#pragma unroll
            for (int h = 0; h < NHEADS; ++h)
                z[h] = hp[h * 8 + 0] * (d[h] / (hp[h * 8 + 6] * mn + 1e-8f));
        }
        // local softmax stats
        float tmp[NHEADS];
#pragma unroll
        for (int h = 0; h < NHEADS; ++h) tmp[h] = z[h];
        blockReduce5(tmp, redb, fin, tid, true);   // local max
#pragma unroll
        for (int h = 0; h < NHEADS; ++h) {
            lmax[h] = fin[h];
            ex[h] = __expf(z[h] - lmax[h]);
            tmp[h] = (pq == 0) ? ex[h] : 0.f;
        }
        blockReduce5(tmp, redb, fin, tid, false);  // local sum(exp)
        if (tid < NHEADS) {
            float lm = lmax[tid], ls = fin[tid];
            float* st0 = stats + r * 10 + tid * 2;
            st0[0] = lm; st0[1] = ls;
#pragma unroll
            for (int c = 0; c < CSZ; ++c)
                if (c != (int)r) {
                    uint32_t a = pb[c] + (OFF_STATS + r * 10 + tid * 2) * 4;
                    st_remote(a, lm); st_remote(a + 4, ls);
                }
        }
        // halo ingredients: my s=0 -> left peer's haloR; my s=127 -> right peer's haloL
        if (tid == 0) {
            float4 wp4 = RW4[0]; float wpv[5] = {wp4.x, wp4.y, wp4.z, wp4.w, wwL[0]};
#pragma unroll
            for (int h = 0; h < NHEADS; ++h) {
                uint32_t a = pb[left] + (OFF_HALO + 10 + h * 2) * 4;
                st_remote(a, ex[h]); st_remote(a + 4, wpv[h]);
            }
        }
        if (tid == (SL - 1) * 4) {
            float4 wp4 = RW4[SL - 1]; float wpv[5] = {wp4.x, wp4.y, wp4.z, wp4.w, wwL[SL - 1]};
#pragma unroll
            for (int h = 0; h < NHEADS; ++h) {
                uint32_t a = pb[right] + (OFF_HALO + h * 2) * 4;
                st_remote(a, ex[h]); st_remote(a + 4, wpv[h]);
            }
        }
        CLUSTER_SYNC();  // CS3: stats + halo ingredients everywhere
        if (tid < NHEADS) {
            float gm = stats[tid * 2];
#pragma unroll
            for (int c = 1; c < CSZ; ++c) gm = fmaxf(gm, stats[c * 10 + tid * 2]);
            float gs = 0.f;
#pragma unroll
            for (int c = 0; c < CSZ; ++c)
                gs += stats[c * 10 + tid * 2 + 1] * __expf(stats[c * 10 + tid * 2] - gm);
            gmx[tid] = gm; gsm[tid] = gs;
        }
        __syncthreads();

        // ---- wg for local slots + halo wg computed locally (no CS4) ----
        if (pq == 0) {
            float4 wp4 = RW4[s]; float wpv[5] = {wp4.x, wp4.y, wp4.z, wp4.w, wwL[s]};
#pragma unroll
            for (int h = 0; h < NHEADS; ++h) {
                float wc = ex[h] * __expf(lmax[h] - gmx[h]) / gsm[h];
                float g  = hp[h * 8 + 1];
                wgb[h * 130 + s + 1] = g * wc + (1.f - g) * wpv[h];
            }
        }
        if (tid >= 448 && tid < 448 + NHEADS) {        // left halo (from left peer's s=127)
            int h = tid - 448;
            float lmL = stats[left * 10 + h * 2];
            float wc = halo[h * 2] * __expf(lmL - gmx[h]) / gsm[h];
            float g  = hp[h * 8 + 1];
            wgb[h * 130 + 0] = g * wc + (1.f - g) * halo[h * 2 + 1];
        }
        if (tid >= 456 && tid < 456 + NHEADS) {        // right halo (from right peer's s=0)
            int h = tid - 456;
            float lmR = stats[right * 10 + h * 2];
            float wc = halo[10 + h * 2] * __expf(lmR - gmx[h]) / gsm[h];
            float g  = hp[h * 8 + 1];
            wgb[h * 130 + 129] = g * wc + (1.f - g) * halo[10 + h * 2 + 1];
        }
        __syncthreads();

        // ---- F: shift + sharpen ----
        float wt[NHEADS];
        if (tid < SL) {
#pragma unroll
            for (int h = 0; h < NHEADS; ++h) {
                float wsh = hp[h * 8 + 3] * wgb[h * 130 + tid + 2]
                          + hp[h * 8 + 4] * wgb[h * 130 + tid + 1]
                          + hp[h * 8 + 5] * wgb[h * 130 + tid];
                wt[h] = __powf(fmaxf(wsh, 0.f), hp[h * 8 + 2]);
            }
        }
#pragma unroll
        for (int h = 0; h < NHEADS; ++h) tmp[h] = (tid < SL) ? wt[h] : 0.f;
        blockReduce5(tmp, redb, fin, tid, false);  // local sum(wt)
        if (tid < NHEADS) {
            float lv = fin[tid];
            ssum[r * 5 + tid] = lv;
#pragma unroll
            for (int c = 0; c < CSZ; ++c)
                if (c != (int)r) st_remote(pb[c] + (OFF_SSUM + r * 5 + tid) * 4, lv);
        }
        CLUSTER_SYNC();  // CS5: sharpen sums everywhere
        if (tid < SL) {
            float wn[NHEADS];
#pragma unroll
            for (int h = 0; h < NHEADS; ++h) {
                float gsumw = ssum[h] + ssum[5 + h] + ssum[10 + h] + ssum[15 + h];
                wn[h] = wt[h] / (gsumw + 1e-8f);
            }
            RW4[tid] = make_float4(wn[0], wn[1], wn[2], wn[3]);
            wwL[tid] = wn[4]; wwb[tid] = wn[4];
        }
        __syncthreads();

        // ---- G: memory write (erase+add) ----
        {
            float wv = wwb[s];
            float* mr = Mem + s * MEMP + pq * 16;
#pragma unroll
            for (int j = 0; j < 4; ++j) {
                float4 e4 = EV4[pq * 4 + j];
                float4 a4 = AV4[pq * 4 + j];
                float m0 = mr[4 * j], m1 = mr[4 * j + 1], m2 = mr[4 * j + 2], m3 = mr[4 * j + 3];
                mr[4 * j]     = m0 * (1.f - wv * e4.x) + wv * a4.x;
                mr[4 * j + 1] = m1 * (1.f - wv * e4.y) + wv * a4.y;
                mr[4 * j + 2] = m2 * (1.f - wv * e4.z) + wv * a4.z;
                mr[4 * j + 3] = m3 * (1.f - wv * e4.w) + wv * a4.w;
            }
        }
        __syncthreads();

        // ---- H: read partials — each Mem element loaded once for all 4 heads ----
        {
            const int m  = tid & 63;
            const int ng = tid >> 6;          // 8 n-groups of 16
            float a0 = 0.f, a1 = 0.f, a2 = 0.f, a3 = 0.f;
            const int n0 = ng * 16;
#pragma unroll
            for (int n = n0; n < n0 + 16; ++n) {
                float mv = Mem[n * MEMP + m];
                float4 rv = RW4[n];
                a0 = fmaf(mv, rv.x, a0); a1 = fmaf(mv, rv.y, a1);
                a2 = fmaf(mv, rv.z, a2); a3 = fmaf(mv, rv.w, a3);
            }
            buf[ng * 256 + 0 * 64 + m] = a0;
            buf[ng * 256 + 1 * 64 + m] = a1;
            buf[ng * 256 + 2 * 64 + m] = a2;
            buf[ng * 256 + 3 * 64 + m] = a3;
        }
        __syncthreads();
        if (tid < 256) {
            float v = 0.f;
#pragma unroll
            for (int ng = 0; ng < 8; ++ng) v += buf[ng * 256 + tid];
            rpart[r * 256 + tid] = v;
#pragma unroll
            for (int c = 0; c < CSZ; ++c)
                if (c != (int)r) st_remote(pb[c] + (OFF_RPART + r * 256 + tid) * 4, v);
        }
        CLUSTER_SYNC();  // CS6: read partials everywhere
        if (tid < 256)
            rvec[tid] = rpart[tid] + rpart[256 + tid] + rpart[512 + tid] + rpart[768 + tid];
        __syncthreads();
    }
}

extern "C" void kernel_launch(void* const* d_in, const int* in_sizes, int n_in,
                              void* d_out, int out_size) {
    const float* x  = (const float*)d_in[0];
    const float* Wc = (const float*)d_in[1];
    const float* bc = (const float*)d_in[2];
    const float* hk = (const float*)d_in[3];
    const float* hb = (const float*)d_in[4];
    float* out = (float*)d_out;

    const size_t smem = SMEM_FLOATS * sizeof(float);
    cudaFuncSetAttribute(ntm_kernel, cudaFuncAttributeMaxDynamicSharedMemorySize, (int)smem);
    ntm_kernel<<<BATCH * CSZ, NT, smem>>>(x, Wc, bc, hk, hb, out);
}

// round 5
// speedup vs baseline: 2.3409x; 1.2824x over previous
#include <cuda_runtime.h>
#include <cstdint>
#include <math.h>

#define BATCH   32
#define TT      32
#define DIN     128
#define CSZ     4        // CTAs per batch (cluster)
#define SL      128      // slots per CTA
#define ML      64
#define CTRLD   256
#define NHEADS  5
#define NT      512
#define MEMP    65
#define KC1     192      // mm1 k-rows cached in SMEM (i=0..5 of stride-32)

// ---- SMEM layout (float offsets) ----
#define OFF_MEM   0        // 8320
#define OFF_BUF   8320     // 2048 : mm2 partials, then GH partials
#define OFF_PX    10368    // 1920 : instr partials [cta][480]; later rpart (1024)
#define OFF_WGB   11392    // 650  : wg with halos (reuses px tail, disjoint lifetime)
#define OFF_RW4   12288    // 512  : read weights [slot] float4
#define OFF_WW    12800    // 128
#define OFF_CTRL  12928    // 384  : [x_t (prefetched) | rvec]
#define OFF_H64   13312    // 64   : local h chunk
#define OFF_KV    13376    // 320
#define OFF_EV    13696    // 64
#define OFF_AV    13760    // 64
#define OFF_HP    13824    // 40   : per head [beta,g,t,s0,s1,s2,-,-]
#define OFF_KRED  13864    // 10   : key-norm^2 warp partials
#define OFF_STATS 13874    // 20   : [cta][head] sum(exp)
#define OFF_HALO  13894    // 20   : L(ex,wp)x5, R(ex,wp)x5
#define OFF_SSUM  13914    // 20
#define OFF_REDB  13934    // 80
#define OFF_FIN   14014    // 8
#define OFF_BCS   14022    // 64
#define OFF_HBS   14086    // 480
#define OFF_SWC   14568    // 192*64 = 12288 (mm1 cache, transposed [grp][k] float4)
#define OFF_SHK   26856    // 64*240*2 = 30720 (mm2 local rows, float2, stride 240)
#define SMEM_FLOATS 57576  // 230304 bytes

__device__ __forceinline__ float sigmoidf_(float v) { return 1.f / (1.f + __expf(-v)); }
__device__ __forceinline__ float softplusf_(float v) { return v > 20.f ? v : log1pf(__expf(v)); }

__device__ __forceinline__ uint32_t smem_u32(const void* p) {
    uint32_t a;
    asm("{ .reg .u64 t; cvta.to.shared.u64 t, %1; cvt.u32.u64 %0, t; }" : "=r"(a) : "l"(p));
    return a;
}
__device__ __forceinline__ uint32_t mapa_u32(uint32_t a, uint32_t rank) {
    uint32_t r;
    asm("mapa.shared::cluster.u32 %0, %1, %2;" : "=r"(r) : "r"(a), "r"(rank));
    return r;
}
__device__ __forceinline__ void st_remote(uint32_t a, float v) {
    asm volatile("st.shared::cluster.f32 [%0], %1;" :: "r"(a), "f"(v) : "memory");
}
__device__ __forceinline__ void st_remote64(uint32_t a, unsigned long long v) {
    asm volatile("st.shared::cluster.u64 [%0], %1;" :: "r"(a), "l"(v) : "memory");
}
__device__ __forceinline__ uint32_t ctarank() {
    uint32_t r; asm("mov.u32 %0, %%cluster_ctarank;" : "=r"(r)); return r;
}
#define CLUSTER_SYNC() do { \
    asm volatile("barrier.cluster.arrive.aligned;" ::: "memory"); \
    asm volatile("barrier.cluster.wait.aligned;" ::: "memory"); } while (0)

__device__ __forceinline__ unsigned long long pack2(float a, float b) {
    return (unsigned long long)__float_as_uint(a) |
           ((unsigned long long)__float_as_uint(b) << 32);
}

// block sum-reduce of 5 values per thread. Result in fin[0..4]. 2 syncthreads.
__device__ __forceinline__ void blockSum5(float* v, float* redb, float* fin, int tid) {
    const int lane = tid & 31, warp = tid >> 5;
#pragma unroll
    for (int o = 16; o > 0; o >>= 1)
#pragma unroll
        for (int h = 0; h < NHEADS; ++h)
            v[h] += __shfl_xor_sync(0xffffffffu, v[h], o);
    if (lane == 0)
#pragma unroll
        for (int h = 0; h < NHEADS; ++h) redb[warp * NHEADS + h] = v[h];
    __syncthreads();
    if (tid < NHEADS) {
        float acc = redb[tid];
#pragma unroll
        for (int w = 1; w < NT / 32; ++w) acc += redb[w * NHEADS + tid];
        fin[tid] = acc;
    }
    __syncthreads();
}

__global__ __launch_bounds__(NT, 1) __cluster_dims__(CSZ, 1, 1)
void ntm_kernel(const float* __restrict__ x, const float* __restrict__ Wc,
                const float* __restrict__ bc, const float* __restrict__ hk,
                const float* __restrict__ hb, float* __restrict__ out)
{
    extern __shared__ float sm[];
    float* Mem   = sm + OFF_MEM;
    float* buf   = sm + OFF_BUF;
    float* px    = sm + OFF_PX;     // instr partials [c][480]
    float* rpart = sm + OFF_PX;     // reuse after parse
    float* wgb   = sm + OFF_WGB;    // reuse px tail after parse
    float4* RW4  = reinterpret_cast<float4*>(sm + OFF_RW4);
    float* wwL   = sm + OFF_WW;
    float* ctrl  = sm + OFF_CTRL;
    float* h64   = sm + OFF_H64;
    float* kvec  = sm + OFF_KV;
    float4* KV4  = reinterpret_cast<float4*>(kvec);
    float* evec  = sm + OFF_EV;
    float* avec  = sm + OFF_AV;
    float* hp    = sm + OFF_HP;
    float* kred  = sm + OFF_KRED;
    float* stats = sm + OFF_STATS;
    float* halo  = sm + OFF_HALO;
    float* ssum  = sm + OFF_SSUM;
    float* redb  = sm + OFF_REDB;
    float* fin   = sm + OFF_FIN;
    float* bcs   = sm + OFF_BCS;
    float* hbs   = sm + OFF_HBS;
    float4* SWC4T = reinterpret_cast<float4*>(sm + OFF_SWC);
    float2* SHK2  = reinterpret_cast<float2*>(sm + OFF_SHK);

    const int tid  = threadIdx.x;
    const int b    = blockIdx.x >> 2;
    const int wrp  = tid >> 5;
    const int lane = tid & 31;
    const uint32_t r = ctarank();
    const uint32_t left  = (r + 3) & 3;
    const uint32_t right = (r + 1) & 3;

    const uint32_t sbase = smem_u32(sm);
    uint32_t pb[CSZ];
#pragma unroll
    for (int c = 0; c < CSZ; ++c) pb[c] = mapa_u32(sbase, c);

    // ---- init state + caches ----
    for (int i = tid; i < SL * MEMP; i += NT) Mem[i] = 0.f;
    for (int i = tid; i < 512; i += NT) (sm + OFF_RW4)[i] = 0.f;
    if (tid < SL) wwL[tid] = 0.f;
    if (tid < DIN)      ctrl[tid] = x[(b * TT) * DIN + tid];  // x_0
    else if (tid < 384) ctrl[tid] = 0.f;                      // r = 0
    if (tid < 64)  bcs[tid] = bc[r * 64 + tid];
    if (tid < 478) hbs[tid] = hb[tid];
    {
        const float4* W4 = reinterpret_cast<const float4*>(Wc);
        for (int i = tid; i < 16 * KC1; i += NT) {
            int w = i / KC1, k = i - w * KC1;
            SWC4T[i] = W4[k * 64 + (int)r * 16 + w];
        }
        const float2* H2 = reinterpret_cast<const float2*>(hk);
        for (int i = tid; i < 64 * 239; i += NT) {
            int kk = i / 239, p = i - kk * 239;
            SHK2[kk * 240 + p] = H2[((int)r * 64 + kk) * 239 + p];
        }
    }
    __syncthreads();
    CLUSTER_SYNC();

    for (int t = 0; t < TT; ++t) {
        // ---- B: mm1, warp-owned columns, shuffle reduce ----
        {
            float a0 = 0.f, a1 = 0.f, a2 = 0.f, a3 = 0.f;
            const float4* cb = SWC4T + wrp * KC1;
#pragma unroll
            for (int i = 0; i < 6; ++i) {
                int k = lane + 32 * i;
                float c = ctrl[k];
                float4 wv = cb[k];
                a0 = fmaf(c, wv.x, a0); a1 = fmaf(c, wv.y, a1);
                a2 = fmaf(c, wv.z, a2); a3 = fmaf(c, wv.w, a3);
            }
            const float4* W4 = reinterpret_cast<const float4*>(Wc) + (int)r * 16 + wrp;
#pragma unroll
            for (int i = 6; i < 12; ++i) {
                int k = lane + 32 * i;
                float c = ctrl[k];
                float4 wv = W4[k * 64];
                a0 = fmaf(c, wv.x, a0); a1 = fmaf(c, wv.y, a1);
                a2 = fmaf(c, wv.z, a2); a3 = fmaf(c, wv.w, a3);
            }
#pragma unroll
            for (int o = 16; o > 0; o >>= 1) {
                a0 += __shfl_xor_sync(0xffffffffu, a0, o);
                a1 += __shfl_xor_sync(0xffffffffu, a1, o);
                a2 += __shfl_xor_sync(0xffffffffu, a2, o);
                a3 += __shfl_xor_sync(0xffffffffu, a3, o);
            }
            if (lane < 4) {
                float av = (lane == 0) ? a0 : (lane == 1) ? a1 : (lane == 2) ? a2 : a3;
                float hv = tanhf(av + bcs[4 * wrp + lane]);
                h64[4 * wrp + lane] = hv;
                if (t == TT - 1) out[b * CTRLD + (int)r * 64 + 4 * wrp + lane] = hv;
            }
        }
        __syncthreads();  // S1

        // ---- C: mm2 partial (local 64 k-rows, full 478 cols) ----
        {
            const int p  = tid & 255;
            const int ks = tid >> 8;
            if (p < 239) {
                float b0 = 0.f, b1 = 0.f;
                const int k0 = ks * 32;
#pragma unroll 8
                for (int kk = k0; kk < k0 + 32; ++kk) {
                    float hv = h64[kk];
                    float2 wv = SHK2[kk * 240 + p];
                    b0 = fmaf(hv, wv.x, b0); b1 = fmaf(hv, wv.y, b1);
                }
                buf[ks * 512 + p]       = b0;
                buf[ks * 512 + 256 + p] = b1;
            }
        }
        __syncthreads();  // S2
        if (tid < 239) {
            float v0 = buf[tid] + buf[512 + tid];
            float v1 = buf[256 + tid] + buf[768 + tid];
            px[r * 480 + 2 * tid]     = v0;
            px[r * 480 + 2 * tid + 1] = v1;
            unsigned long long pk = pack2(v0, v1);
#pragma unroll
            for (int c = 0; c < CSZ; ++c)
                if (c != (int)r)
                    st_remote64(pb[c] + (OFF_PX + (int)r * 480 + 2 * tid) * 4, pk);
        }
        CLUSTER_SYNC();  // CS2: instr partials everywhere

        // ---- D: parse (fold 4-way partial sum) ----
        if (tid < 320) {
            int h = tid >> 6, m = tid & 63;
            int base = (h < 4 ? h * 70 : 280) + m;
            float v = px[base] + px[480 + base] + px[960 + base] + px[1440 + base] + hbs[base];
            kvec[tid] = v;
            float sq = v * v;
#pragma unroll
            for (int o = 16; o > 0; o >>= 1) sq += __shfl_xor_sync(0xffffffffu, sq, o);
            if (lane == 0) kred[wrp] = sq;   // warps 0..9 cover the 5 heads (2 each)
        } else if (tid < 384) {
            int m = tid - 320, base = 350 + m;
            evec[m] = px[base] + px[480 + base] + px[960 + base] + px[1440 + base] + hbs[base];
        } else if (tid < 448) {
            int m = tid - 384, base = 414 + m;
            avec[m] = px[base] + px[480 + base] + px[960 + base] + px[1440 + base] + hbs[base];
        } else if (tid < 448 + NHEADS) {
            int h = tid - 448;
            int base = (h < 4 ? h * 70 : 280);
            float sv[6];
#pragma unroll
            for (int j = 0; j < 6; ++j) {
                int idx = base + 64 + j;
                sv[j] = px[idx] + px[480 + idx] + px[960 + idx] + px[1440 + idx] + hbs[idx];
            }
            hp[h * 8 + 0] = __expf(sv[0]);
            hp[h * 8 + 1] = sigmoidf_(sv[1]);
            float s0 = sv[2], s1 = sv[3], s2 = sv[4];
            float mx = fmaxf(s0, fmaxf(s1, s2));
            float e0 = __expf(s0 - mx), e1 = __expf(s1 - mx), e2 = __expf(s2 - mx);
            float inv = 1.f / (e0 + e1 + e2);
            hp[h * 8 + 3] = e0 * inv; hp[h * 8 + 4] = e1 * inv; hp[h * 8 + 5] = e2 * inv;
            hp[h * 8 + 2] = softplusf_(sv[5]) + 1.f;
        }
        __syncthreads();  // S3

        // ---- E: sim + norm (4 threads/slot), softmax without max-pass ----
        const int s  = tid >> 2;
        const int pq = tid & 3;
        float ex[NHEADS], tmp[NHEADS];
        {
            float d[NHEADS] = {0.f, 0.f, 0.f, 0.f, 0.f};
            float nn = 0.f;
            const float* mr = Mem + s * MEMP + pq * 16;
#pragma unroll
            for (int j = 0; j < 4; ++j) {
                float m0 = mr[4 * j], m1 = mr[4 * j + 1], m2 = mr[4 * j + 2], m3 = mr[4 * j + 3];
                nn = fmaf(m0, m0, nn); nn = fmaf(m1, m1, nn);
                nn = fmaf(m2, m2, nn); nn = fmaf(m3, m3, nn);
#pragma unroll
                for (int h = 0; h < NHEADS; ++h) {
                    float4 kq = KV4[h * 16 + pq * 4 + j];
                    d[h] = fmaf(m0, kq.x, d[h]); d[h] = fmaf(m1, kq.y, d[h]);
                    d[h] = fmaf(m2, kq.z, d[h]); d[h] = fmaf(m3, kq.w, d[h]);
                }
            }
#pragma unroll
            for (int o = 1; o <= 2; o <<= 1) {
#pragma unroll
                for (int h = 0; h < NHEADS; ++h) d[h] += __shfl_xor_sync(0xffffffffu, d[h], o);
                nn += __shfl_xor_sync(0xffffffffu, nn, o);
            }
            float mn = sqrtf(nn);
#pragma unroll
            for (int h = 0; h < NHEADS; ++h) {
                float kn = sqrtf(kred[2 * h] + kred[2 * h + 1]);
                float z = hp[h * 8 + 0] * (d[h] / (kn * mn + 1e-8f));
                ex[h] = __expf(z);
                tmp[h] = (pq == 0) ? ex[h] : 0.f;
            }
        }
        blockSum5(tmp, redb, fin, tid);   // S4,S5 -> fin = local sum(exp)
        if (tid < NHEADS) {
            float ls = fin[tid];
            stats[r * 5 + tid] = ls;
#pragma unroll
            for (int c = 0; c < CSZ; ++c)
                if (c != (int)r) st_remote(pb[c] + (OFF_STATS + (int)r * 5 + tid) * 4, ls);
        }
        if (tid == 0) {   // my slot 0 -> left peer's right halo
            float4 wp4 = RW4[0]; float wpv[5] = {wp4.x, wp4.y, wp4.z, wp4.w, wwL[0]};
#pragma unroll
            for (int h = 0; h < NHEADS; ++h)
                st_remote64(pb[left] + (OFF_HALO + 10 + h * 2) * 4, pack2(ex[h], wpv[h]));
        }
        if (tid == (SL - 1) * 4) {  // my slot 127 -> right peer's left halo
            float4 wp4 = RW4[SL - 1]; float wpv[5] = {wp4.x, wp4.y, wp4.z, wp4.w, wwL[SL - 1]};
#pragma unroll
            for (int h = 0; h < NHEADS; ++h)
                st_remote64(pb[right] + (OFF_HALO + h * 2) * 4, pack2(ex[h], wpv[h]));
        }
        CLUSTER_SYNC();  // CS3

        // ---- wg (gated interpolate) + halos ----
        if (pq == 0) {
            float4 wp4 = RW4[s]; float wpv[5] = {wp4.x, wp4.y, wp4.z, wp4.w, wwL[s]};
#pragma unroll
            for (int h = 0; h < NHEADS; ++h) {
                float gs = stats[h] + stats[5 + h] + stats[10 + h] + stats[15 + h];
                float wc = ex[h] / gs;
                float g  = hp[h * 8 + 1];
                wgb[h * 130 + s + 1] = g * wc + (1.f - g) * wpv[h];
            }
        }
        if (tid >= 448 && tid < 448 + NHEADS) {   // left halo
            int h = tid - 448;
            float gs = stats[h] + stats[5 + h] + stats[10 + h] + stats[15 + h];
            float wc = halo[h * 2] / gs;
            float g  = hp[h * 8 + 1];
            wgb[h * 130 + 0] = g * wc + (1.f - g) * halo[h * 2 + 1];
        }
        if (tid >= 456 && tid < 456 + NHEADS) {   // right halo
            int h = tid - 456;
            float gs = stats[h] + stats[5 + h] + stats[10 + h] + stats[15 + h];
            float wc = halo[10 + h * 2] / gs;
            float g  = hp[h * 8 + 1];
            wgb[h * 130 + 129] = g * wc + (1.f - g) * halo[10 + h * 2 + 1];
        }
        __syncthreads();  // S6

        // ---- F: shift + sharpen ----
        float wt[NHEADS];
        if (tid < SL) {
#pragma unroll
            for (int h = 0; h < NHEADS; ++h) {
                float wsh = hp[h * 8 + 3] * wgb[h * 130 + tid + 2]
                          + hp[h * 8 + 4] * wgb[h * 130 + tid + 1]
                          + hp[h * 8 + 5] * wgb[h * 130 + tid];
                wt[h] = __powf(fmaxf(wsh, 0.f), hp[h * 8 + 2]);
            }
        }
#pragma unroll
        for (int h = 0; h < NHEADS; ++h) tmp[h] = (tid < SL) ? wt[h] : 0.f;
        blockSum5(tmp, redb, fin, tid);   // S7,S8
        if (tid < NHEADS) {
            float lv = fin[tid];
            ssum[r * 5 + tid] = lv;
#pragma unroll
            for (int c = 0; c < CSZ; ++c)
                if (c != (int)r) st_remote(pb[c] + (OFF_SSUM + (int)r * 5 + tid) * 4, lv);
        }
        CLUSTER_SYNC();  // CS5
        if (tid < SL) {
            float wn[NHEADS];
#pragma unroll
            for (int h = 0; h < NHEADS; ++h) {
                float gsw = ssum[h] + ssum[5 + h] + ssum[10 + h] + ssum[15 + h];
                wn[h] = wt[h] / (gsw + 1e-8f);
            }
            RW4[tid] = make_float4(wn[0], wn[1], wn[2], wn[3]);
            wwL[tid] = wn[4];
        } else if (tid < 256 && t + 1 < TT) {
            ctrl[tid - 128] = x[(b * TT + t + 1) * DIN + (tid - 128)];  // prefetch x_{t+1}
        }
        __syncthreads();  // S9

        // ---- GH fused: Mem erase/add + read partials in ONE pass ----
        {
            const int m  = tid & 63;
            const int ng = tid >> 6;
            const float ev = evec[m], av = avec[m];
            float a0 = 0.f, a1 = 0.f, a2 = 0.f, a3 = 0.f;
            const int n0 = ng * 16;
#pragma unroll
            for (int n = n0; n < n0 + 16; ++n) {
                float wv = wwL[n];
                float* mp = Mem + n * MEMP + m;
                float mv = *mp;
                mv = mv * (1.f - wv * ev) + wv * av;
                *mp = mv;
                float4 rv = RW4[n];
                a0 = fmaf(mv, rv.x, a0); a1 = fmaf(mv, rv.y, a1);
                a2 = fmaf(mv, rv.z, a2); a3 = fmaf(mv, rv.w, a3);
            }
            buf[ng * 256 + 0 * 64 + m] = a0;
            buf[ng * 256 + 1 * 64 + m] = a1;
            buf[ng * 256 + 2 * 64 + m] = a2;
            buf[ng * 256 + 3 * 64 + m] = a3;
        }
        __syncthreads();  // S10
        if (tid < 128) {
            float v0 = 0.f, v1 = 0.f;
#pragma unroll
            for (int ng = 0; ng < 8; ++ng) {
                v0 += buf[ng * 256 + 2 * tid];
                v1 += buf[ng * 256 + 2 * tid + 1];
            }
            rpart[r * 256 + 2 * tid]     = v0;
            rpart[r * 256 + 2 * tid + 1] = v1;
            unsigned long long pk = pack2(v0, v1);
#pragma unroll
            for (int c = 0; c < CSZ; ++c)
                if (c != (int)r)
                    st_remote64(pb[c] + (OFF_PX + (int)r * 256 + 2 * tid) * 4, pk);
        }
        CLUSTER_SYNC();  // CS6
        if (tid < 256)
            ctrl[128 + tid] = rpart[tid] + rpart[256 + tid] + rpart[512 + tid] + rpart[768 + tid];
        __syncthreads();  // S11 (loop boundary)
    }
}

extern "C" void kernel_launch(void* const* d_in, const int* in_sizes, int n_in,
                              void* d_out, int out_size) {
    const float* x  = (const float*)d_in[0];
    const float* Wc = (const float*)d_in[1];
    const float* bc = (const float*)d_in[2];
    const float* hk = (const float*)d_in[3];
    const float* hb = (const float*)d_in[4];
    float* out = (float*)d_out;

    const size_t smem = SMEM_FLOATS * sizeof(float);
    cudaFuncSetAttribute(ntm_kernel, cudaFuncAttributeMaxDynamicSharedMemorySize, (int)smem);
    ntm_kernel<<<BATCH * CSZ, NT, smem>>>(x, Wc, bc, hk, hb, out);
}

// round 6
// speedup vs baseline: 2.3945x; 1.0229x over previous
#include <cuda_runtime.h>
#include <cstdint>
#include <math.h>

#define BATCH   32
#define TT      32
#define DIN     128
#define CSZ     4
#define SL      128
#define CTRLD   256
#define NHEADS  5
#define NT      512
#define MEMP    65
#define KC1     160      // mm1 k-rows cached in SMEM

// ---- SMEM layout (float offsets) ----
#define OFF_MEM    0        // 8320
#define OFF_PX     8320     // 1920 instr partials [cta][480]; reused as rpart[4][256]
#define OFF_EXG    10240    // 650 : ex with halos [h][130]
#define OFF_HALO   10890    // 20  : L{ex,wp}x5, R{ex,wp}x5
#define OFF_STATS  10910    // 20  : [cta][head] sum(exp)
#define OFF_SSUM   10930    // 20  : [cta][head] sum(wt)
#define OFF_REDB   10950    // 80
#define OFF_KRED   11030    // 10
#define OFF_HP     11040    // 40
#define OFF_PINV   11080    // 8
#define OFF_RWA    11088    // 512 : rw wt ping (float4/slot)
#define OFF_RWB    11600    // 512 : rw wt pong
#define OFF_WWA    12112    // 128
#define OFF_WWB    12240    // 128
#define OFF_XB     12368    // 256 : x double buffer
#define OFF_RVEC   12624    // 256
#define OFF_H64    12880    // 64
#define OFF_KV     12944    // 320
#define OFF_EV     13264    // 64
#define OFF_AV     13328    // 64
#define OFF_BCS    13392    // 64
#define OFF_HBS    13456    // 480
#define OFF_BUF    13936    // 2048 GH partials
#define OFF_SWC    15984    // 160*64 = 10240 (mm1 cache, [grp][k] float4)
#define OFF_SHK    26224    // 64*480 = 30720 (mm2 cache, k-major)
#define SMEM_FLOATS 56944   // 227776 bytes

__device__ __forceinline__ float sigmoidf_(float v) { return 1.f / (1.f + __expf(-v)); }
__device__ __forceinline__ float softplusf_(float v) { return v > 20.f ? v : log1pf(__expf(v)); }

__device__ __forceinline__ uint32_t smem_u32(const void* p) {
    uint32_t a;
    asm("{ .reg .u64 t; cvta.to.shared.u64 t, %1; cvt.u32.u64 %0, t; }" : "=r"(a) : "l"(p));
    return a;
}
__device__ __forceinline__ uint32_t mapa_u32(uint32_t a, uint32_t rank) {
    uint32_t r;
    asm("mapa.shared::cluster.u32 %0, %1, %2;" : "=r"(r) : "r"(a), "r"(rank));
    return r;
}
__device__ __forceinline__ void st_remote(uint32_t a, float v) {
    asm volatile("st.shared::cluster.f32 [%0], %1;" :: "r"(a), "f"(v) : "memory");
}
__device__ __forceinline__ void st_remote64(uint32_t a, unsigned long long v) {
    asm volatile("st.shared::cluster.u64 [%0], %1;" :: "r"(a), "l"(v) : "memory");
}
__device__ __forceinline__ uint32_t ctarank() {
    uint32_t r; asm("mov.u32 %0, %%cluster_ctarank;" : "=r"(r)); return r;
}
#define CLUSTER_SYNC() do { \
    asm volatile("barrier.cluster.arrive.aligned;" ::: "memory"); \
    asm volatile("barrier.cluster.wait.aligned;" ::: "memory"); } while (0)

__device__ __forceinline__ unsigned long long pack2(float a, float b) {
    return (unsigned long long)__float_as_uint(a) |
           ((unsigned long long)__float_as_uint(b) << 32);
}

__global__ __launch_bounds__(NT, 1) __cluster_dims__(CSZ, 1, 1)
void ntm_kernel(const float* __restrict__ x, const float* __restrict__ Wc,
                const float* __restrict__ bc, const float* __restrict__ hk,
                const float* __restrict__ hb, float* __restrict__ out)
{
    extern __shared__ float sm[];
    float* Mem   = sm + OFF_MEM;
    float* px    = sm + OFF_PX;
    float* rpart = sm + OFF_PX;
    float* exg   = sm + OFF_EXG;
    float* halo  = sm + OFF_HALO;
    float* stats = sm + OFF_STATS;
    float* ssum  = sm + OFF_SSUM;
    float* redb  = sm + OFF_REDB;
    float* kred  = sm + OFF_KRED;
    float* hp    = sm + OFF_HP;
    float* pinv  = sm + OFF_PINV;
    float* xb    = sm + OFF_XB;
    float* rvec  = sm + OFF_RVEC;
    float* h64   = sm + OFF_H64;
    float* kvec  = sm + OFF_KV;
    float4* KV4  = reinterpret_cast<float4*>(kvec);
    float* evec  = sm + OFF_EV;
    float* avec  = sm + OFF_AV;
    float* bcs   = sm + OFF_BCS;
    float* hbs   = sm + OFF_HBS;
    float* buf   = sm + OFF_BUF;
    float4* SWC4T = reinterpret_cast<float4*>(sm + OFF_SWC);
    float* SHK   = sm + OFF_SHK;

    const int tid  = threadIdx.x;
    const int b    = blockIdx.x >> 2;
    const int wrp  = tid >> 5;
    const int lane = tid & 31;
    const uint32_t r = ctarank();
    const uint32_t left  = (r + 3) & 3;
    const uint32_t right = (r + 1) & 3;

    const uint32_t sbase = smem_u32(sm);
    uint32_t pb[CSZ];
#pragma unroll
    for (int c = 0; c < CSZ; ++c) pb[c] = mapa_u32(sbase, c);

    // ---- init ----
    for (int i = tid; i < SL * MEMP; i += NT) Mem[i] = 0.f;
    for (int i = tid; i < 512; i += NT) (sm + OFF_RWA)[i] = 0.f;
    if (tid < SL)  (sm + OFF_WWA)[tid] = 0.f;
    if (tid < 256) rvec[tid] = 0.f;
    if (tid < DIN) xb[tid] = x[(b * TT) * DIN + tid];
    if (tid < 8)   pinv[tid] = 1.f;
    if (tid < 64)  bcs[tid] = bc[r * 64 + tid];
    if (tid < 478) hbs[tid] = hb[tid];
    {
        const float4* W4 = reinterpret_cast<const float4*>(Wc);
        for (int i = tid; i < 16 * KC1; i += NT) {
            int w = i / KC1, k = i - w * KC1;
            SWC4T[i] = W4[k * 64 + (int)r * 16 + w];
        }
        for (int kk = 0; kk < 64; ++kk)
            if (tid < 478)
                SHK[kk * 480 + tid] = hk[((int)r * 64 + kk) * 478 + tid];
    }
    __syncthreads();
    CLUSTER_SYNC();

    for (int t = 0; t < TT; ++t) {
        const int par = t & 1;
        float* RWrd = sm + (par ? OFF_RWB : OFF_RWA);
        float* RWwr = sm + (par ? OFF_RWA : OFF_RWB);
        float4* RW4rd = reinterpret_cast<float4*>(RWrd);
        float4* RW4wr = reinterpret_cast<float4*>(RWwr);
        float* wwrd = sm + (par ? OFF_WWB : OFF_WWA);
        float* wwwr = sm + (par ? OFF_WWA : OFF_WWB);
        const float* xbp = xb + par * 128;

        // ---- B: mm1, warp-owned 4 columns, shuffle reduce ----
        {
            float a0 = 0.f, a1 = 0.f, a2 = 0.f, a3 = 0.f;
            const float4* cw = SWC4T + wrp * KC1;
#pragma unroll
            for (int i = 0; i < 4; ++i) {               // x part, cached
                int k = lane + 32 * i;
                float c = xbp[k];
                float4 w = cw[k];
                a0 = fmaf(c, w.x, a0); a1 = fmaf(c, w.y, a1);
                a2 = fmaf(c, w.z, a2); a3 = fmaf(c, w.w, a3);
            }
            {                                           // i=4, r part, cached
                int k = lane + 128;
                float c = rvec[lane];
                float4 w = cw[k];
                a0 = fmaf(c, w.x, a0); a1 = fmaf(c, w.y, a1);
                a2 = fmaf(c, w.z, a2); a3 = fmaf(c, w.w, a3);
            }
            const float4* W4 = reinterpret_cast<const float4*>(Wc) + (int)r * 16 + wrp;
#pragma unroll
            for (int i = 5; i < 12; ++i) {              // r part, streamed from L2
                int k = lane + 32 * i;
                float c = rvec[k - 128];
                float4 w = W4[k * 64];
                a0 = fmaf(c, w.x, a0); a1 = fmaf(c, w.y, a1);
                a2 = fmaf(c, w.z, a2); a3 = fmaf(c, w.w, a3);
            }
#pragma unroll
            for (int o = 16; o > 0; o >>= 1) {
                a0 += __shfl_xor_sync(0xffffffffu, a0, o);
                a1 += __shfl_xor_sync(0xffffffffu, a1, o);
                a2 += __shfl_xor_sync(0xffffffffu, a2, o);
                a3 += __shfl_xor_sync(0xffffffffu, a3, o);
            }
            if (lane < 4) {
                float av = (lane == 0) ? a0 : (lane == 1) ? a1 : (lane == 2) ? a2 : a3;
                float hv = tanhf(av + bcs[4 * wrp + lane]);
                h64[4 * wrp + lane] = hv;
                if (t == TT - 1) out[b * CTRLD + (int)r * 64 + 4 * wrp + lane] = hv;
            }
        }
        __syncthreads();  // S1

        // ---- C: mm2 single pass (1 col/thread, full local k) ----
        if (wrp < 15) {
            float v = 0.f;
#pragma unroll 16
            for (int k = 0; k < 64; ++k)
                v = fmaf(h64[k], SHK[k * 480 + tid], v);
            if (tid < 478) px[r * 480 + tid] = v;
            float vo = __shfl_down_sync(0xffffffffu, v, 1);
            if (!(tid & 1) && tid < 477) {
                unsigned long long pk = pack2(v, vo);
#pragma unroll
                for (int c = 0; c < CSZ; ++c)
                    if (c != (int)r)
                        st_remote64(pb[c] + (OFF_PX + (int)r * 480 + tid) * 4, pk);
            }
        }
        CLUSTER_SYNC();  // CS2

        // ---- D: parse (fold partials) ----
        if (tid < 320) {
            int h = tid >> 6, m = tid & 63;
            int base = (h < 4 ? h * 70 : 280) + m;
            float v = px[base] + px[480 + base] + px[960 + base] + px[1440 + base] + hbs[base];
            kvec[tid] = v;
            float sq = v * v;
#pragma unroll
            for (int o = 16; o > 0; o >>= 1) sq += __shfl_xor_sync(0xffffffffu, sq, o);
            if (lane == 0) kred[wrp] = sq;
        } else if (tid < 384) {
            int m = tid - 320, base = 350 + m;
            evec[m] = px[base] + px[480 + base] + px[960 + base] + px[1440 + base] + hbs[base];
        } else if (tid < 448) {
            int m = tid - 384, base = 414 + m;
            avec[m] = px[base] + px[480 + base] + px[960 + base] + px[1440 + base] + hbs[base];
        } else if (tid < 448 + NHEADS) {
            int h = tid - 448;
            int base = (h < 4 ? h * 70 : 280);
            float sv[6];
#pragma unroll
            for (int j = 0; j < 6; ++j) {
                int idx = base + 64 + j;
                sv[j] = px[idx] + px[480 + idx] + px[960 + idx] + px[1440 + idx] + hbs[idx];
            }
            hp[h * 8 + 0] = __expf(sv[0]);
            hp[h * 8 + 1] = sigmoidf_(sv[1]);
            float s0 = sv[2], s1 = sv[3], s2 = sv[4];
            float mx = fmaxf(s0, fmaxf(s1, s2));
            float e0 = __expf(s0 - mx), e1 = __expf(s1 - mx), e2 = __expf(s2 - mx);
            float inv = 1.f / (e0 + e1 + e2);
            hp[h * 8 + 3] = e0 * inv; hp[h * 8 + 4] = e1 * inv; hp[h * 8 + 5] = e2 * inv;
            hp[h * 8 + 2] = softplusf_(sv[5]) + 1.f;
        }
        __syncthreads();  // S3

        // ---- E: sim + exp (4 threads/slot), one-barrier reduce ----
        const int s  = tid >> 2;
        const int pq = tid & 3;
        float ex[NHEADS];
        {
            float d[NHEADS] = {0.f, 0.f, 0.f, 0.f, 0.f};
            float nn = 0.f;
            const float* mr = Mem + s * MEMP + pq * 16;
#pragma unroll
            for (int j = 0; j < 4; ++j) {
                float m0 = mr[4 * j], m1 = mr[4 * j + 1], m2 = mr[4 * j + 2], m3 = mr[4 * j + 3];
                nn = fmaf(m0, m0, nn); nn = fmaf(m1, m1, nn);
                nn = fmaf(m2, m2, nn); nn = fmaf(m3, m3, nn);
#pragma unroll
                for (int h = 0; h < NHEADS; ++h) {
                    float4 kq = KV4[h * 16 + pq * 4 + j];
                    d[h] = fmaf(m0, kq.x, d[h]); d[h] = fmaf(m1, kq.y, d[h]);
                    d[h] = fmaf(m2, kq.z, d[h]); d[h] = fmaf(m3, kq.w, d[h]);
                }
            }
#pragma unroll
            for (int o = 1; o <= 2; o <<= 1) {
#pragma unroll
                for (int h = 0; h < NHEADS; ++h) d[h] += __shfl_xor_sync(0xffffffffu, d[h], o);
                nn += __shfl_xor_sync(0xffffffffu, nn, o);
            }
            float mn = sqrtf(nn);
#pragma unroll
            for (int h = 0; h < NHEADS; ++h) {
                float kn = sqrtf(kred[2 * h] + kred[2 * h + 1]);
                float z = hp[h * 8 + 0] * (d[h] / (kn * mn + 1e-8f));
                ex[h] = __expf(z);
            }
        }
        if (pq == 0) {
#pragma unroll
            for (int h = 0; h < NHEADS; ++h) exg[h * 130 + s + 1] = ex[h];
        }
        if (tid == 0) {               // slot 0 -> left peer's right halo
            float4 wp4 = RW4rd[0];
            float wpv[5] = {wp4.x * pinv[0], wp4.y * pinv[1], wp4.z * pinv[2],
                            wp4.w * pinv[3], wwrd[0] * pinv[4]};
#pragma unroll
            for (int h = 0; h < NHEADS; ++h)
                st_remote64(pb[left] + (OFF_HALO + 10 + h * 2) * 4, pack2(ex[h], wpv[h]));
        }
        if (tid == (SL - 1) * 4) {    // slot 127 -> right peer's left halo
            float4 wp4 = RW4rd[SL - 1];
            float wpv[5] = {wp4.x * pinv[0], wp4.y * pinv[1], wp4.z * pinv[2],
                            wp4.w * pinv[3], wwrd[SL - 1] * pinv[4]};
#pragma unroll
            for (int h = 0; h < NHEADS; ++h)
                st_remote64(pb[right] + (OFF_HALO + h * 2) * 4, pack2(ex[h], wpv[h]));
        }
        {
            float tmp[NHEADS];
#pragma unroll
            for (int h = 0; h < NHEADS; ++h) tmp[h] = (pq == 0) ? ex[h] : 0.f;
#pragma unroll
            for (int o = 16; o > 0; o >>= 1)
#pragma unroll
                for (int h = 0; h < NHEADS; ++h)
                    tmp[h] += __shfl_xor_sync(0xffffffffu, tmp[h], o);
            if (lane == 0)
#pragma unroll
                for (int h = 0; h < NHEADS; ++h) redb[wrp * 5 + h] = tmp[h];
        }
        __syncthreads();  // S4
        if (tid < NHEADS) {
            float acc = 0.f;
#pragma unroll
            for (int w = 0; w < 16; ++w) acc += redb[w * 5 + tid];
            stats[r * 5 + tid] = acc;
#pragma unroll
            for (int c = 0; c < CSZ; ++c)
                if (c != (int)r) st_remote(pb[c] + (OFF_STATS + (int)r * 5 + tid) * 4, acc);
        }
        CLUSTER_SYNC();  // CS3

        // ---- F fused: wg (3 neighbors) + shift + sharpen ----
        float wt[NHEADS];
        if (tid < SL) {
            float invgs[NHEADS];
#pragma unroll
            for (int h = 0; h < NHEADS; ++h)
                invgs[h] = 1.f / (stats[h] + stats[5 + h] + stats[10 + h] + stats[15 + h]);
            float4 wc4 = RW4rd[tid];
            float wpc[5] = {wc4.x * pinv[0], wc4.y * pinv[1], wc4.z * pinv[2],
                            wc4.w * pinv[3], wwrd[tid] * pinv[4]};
            float wpm[5], wpp[5];
            if (tid > 0) {
                float4 w4 = RW4rd[tid - 1];
                wpm[0] = w4.x * pinv[0]; wpm[1] = w4.y * pinv[1];
                wpm[2] = w4.z * pinv[2]; wpm[3] = w4.w * pinv[3];
                wpm[4] = wwrd[tid - 1] * pinv[4];
            } else {
#pragma unroll
                for (int h = 0; h < NHEADS; ++h) wpm[h] = halo[h * 2 + 1];
            }
            if (tid < SL - 1) {
                float4 w4 = RW4rd[tid + 1];
                wpp[0] = w4.x * pinv[0]; wpp[1] = w4.y * pinv[1];
                wpp[2] = w4.z * pinv[2]; wpp[3] = w4.w * pinv[3];
                wpp[4] = wwrd[tid + 1] * pinv[4];
            } else {
#pragma unroll
                for (int h = 0; h < NHEADS; ++h) wpp[h] = halo[10 + h * 2 + 1];
            }
#pragma unroll
            for (int h = 0; h < NHEADS; ++h) {
                float g = hp[h * 8 + 1];
                float exm = exg[h * 130 + tid];
                float exc = exg[h * 130 + tid + 1];
                float exp_ = exg[h * 130 + tid + 2];
                float wgm = g * (exm * invgs[h]) + (1.f - g) * wpm[h];
                float wgc = g * (exc * invgs[h]) + (1.f - g) * wpc[h];
                float wgp = g * (exp_ * invgs[h]) + (1.f - g) * wpp[h];
                float wsh = hp[h * 8 + 3] * wgp + hp[h * 8 + 4] * wgc + hp[h * 8 + 5] * wgm;
                wt[h] = __powf(fmaxf(wsh, 0.f), hp[h * 8 + 2]);
            }
            RW4wr[tid] = make_float4(wt[0], wt[1], wt[2], wt[3]);
            wwwr[tid] = wt[4];
            // warp reduce (warps 0..3 only)
            float tmp[NHEADS];
#pragma unroll
            for (int h = 0; h < NHEADS; ++h) tmp[h] = wt[h];
#pragma unroll
            for (int o = 16; o > 0; o >>= 1)
#pragma unroll
                for (int h = 0; h < NHEADS; ++h)
                    tmp[h] += __shfl_xor_sync(0xffffffffu, tmp[h], o);
            if (lane == 0)
#pragma unroll
                for (int h = 0; h < NHEADS; ++h) redb[wrp * 5 + h] = tmp[h];
        } else if (tid >= 384 && t + 1 < TT) {
            xb[(1 - par) * 128 + (tid - 384)] = x[(b * TT + t + 1) * DIN + (tid - 384)];
        }
        __syncthreads();  // S7
        if (tid < NHEADS) {
            float acc = redb[tid] + redb[5 + tid] + redb[10 + tid] + redb[15 + tid];
            ssum[r * 5 + tid] = acc;
#pragma unroll
            for (int c = 0; c < CSZ; ++c)
                if (c != (int)r) st_remote(pb[c] + (OFF_SSUM + (int)r * 5 + tid) * 4, acc);
        }
        CLUSTER_SYNC();  // CS5

        // ---- GH fused: Mem erase/add + read partials (unnormalized, inv folded) ----
        {
            const int m  = tid & 63;
            const int ng = tid >> 6;
            const float invW = 1.f / (ssum[4] + ssum[9] + ssum[14] + ssum[19] + 1e-8f);
            const float ev = evec[m] * invW, av = avec[m] * invW;
            if (tid < NHEADS)
                pinv[tid] = 1.f / (ssum[tid] + ssum[5 + tid] + ssum[10 + tid] + ssum[15 + tid] + 1e-8f);
            float a0 = 0.f, a1 = 0.f, a2 = 0.f, a3 = 0.f;
            const int n0 = ng * 16;
#pragma unroll
            for (int n = n0; n < n0 + 16; ++n) {
                float wv = wwwr[n];
                float* mp = Mem + n * MEMP + m;
                float mv = *mp;
                mv = mv * (1.f - wv * ev) + wv * av;
                *mp = mv;
                float4 rv = RW4wr[n];
                a0 = fmaf(mv, rv.x, a0); a1 = fmaf(mv, rv.y, a1);
                a2 = fmaf(mv, rv.z, a2); a3 = fmaf(mv, rv.w, a3);
            }
            buf[ng * 256 + 0 * 64 + m] = a0;
            buf[ng * 256 + 1 * 64 + m] = a1;
            buf[ng * 256 + 2 * 64 + m] = a2;
            buf[ng * 256 + 3 * 64 + m] = a3;
        }
        __syncthreads();  // S10
        if (tid < 128) {
            float v0 = 0.f, v1 = 0.f;
#pragma unroll
            for (int ng = 0; ng < 8; ++ng) {
                v0 += buf[ng * 256 + 2 * tid];
                v1 += buf[ng * 256 + 2 * tid + 1];
            }
            rpart[r * 256 + 2 * tid]     = v0;
            rpart[r * 256 + 2 * tid + 1] = v1;
            unsigned long long pk = pack2(v0, v1);
#pragma unroll
            for (int c = 0; c < CSZ; ++c)
                if (c != (int)r)
                    st_remote64(pb[c] + (OFF_PX + (int)r * 256 + 2 * tid) * 4, pk);
        }
        CLUSTER_SYNC();  // CS6
        if (tid < 256) {
            int h = tid >> 6;
            rvec[tid] = (rpart[tid] + rpart[256 + tid] + rpart[512 + tid] + rpart[768 + tid])
                        * pinv[h];
        }
        __syncthreads();  // S11 (loop boundary)
    }
}

extern "C" void kernel_launch(void* const* d_in, const int* in_sizes, int n_in,
                              void* d_out, int out_size) {
    const float* x  = (const float*)d_in[0];
    const float* Wc = (const float*)d_in[1];
    const float* bc = (const float*)d_in[2];
    const float* hk = (const float*)d_in[3];
    const float* hb = (const float*)d_in[4];
    float* out = (float*)d_out;

    const size_t smem = SMEM_FLOATS * sizeof(float);
    cudaFuncSetAttribute(ntm_kernel, cudaFuncAttributeMaxDynamicSharedMemorySize, (int)smem);
    ntm_kernel<<<BATCH * CSZ, NT, smem>>>(x, Wc, bc, hk, hb, out);
}